// round 1
// baseline (speedup 1.0000x reference)
#include <cuda_runtime.h>
#include <cuda_bf16.h>

#define B_ 2
#define L_ 512
#define V_ 64
#define D_ 128
#define NC_ 8

#define BM 64
#define BN 64
#define SKQ 132   // padded stride (floats) for Q/K/V tiles, keeps float4 alignment
#define SSS 68    // padded stride for score tile

// ---- static device scratch (no allocations allowed) ----
__device__ float g_sumK[B_ * L_ * D_];
__device__ int   g_idx[B_][NC_][L_];
__device__ int   g_cnt[B_][NC_];

// ---------------------------------------------------------------------------
// Kernel 1: sumK[b,l,d] = sum_v key[b,l,v,d]
// ---------------------------------------------------------------------------
__global__ void sumk_kernel(const float* __restrict__ key) {
    int bl = blockIdx.x;          // 0 .. B*L-1
    int d  = threadIdx.x;         // 0 .. 127
    const float* p = key + (size_t)bl * V_ * D_ + d;
    float s = 0.f;
#pragma unroll 8
    for (int v = 0; v < V_; v++) s += p[(size_t)v * D_];
    g_sumK[(size_t)bl * D_ + d] = s;
}

// ---------------------------------------------------------------------------
// Kernel 2: deterministic per-(b,c) index list via warp ballot compaction
// ---------------------------------------------------------------------------
__global__ void build_idx_kernel(const int* __restrict__ label) {
    int c = blockIdx.x, b = blockIdx.y;
    int lane = threadIdx.x;       // 32 threads
    int cnt = 0;
    for (int l0 = 0; l0 < L_; l0 += 32) {
        int l = l0 + lane;
        int lbl = label[b * L_ + l];
        unsigned m = __ballot_sync(0xffffffffu, lbl == c);
        if (lbl == c) {
            int pos = cnt + __popc(m & ((1u << lane) - 1u));
            g_idx[b][c][pos] = l;
        }
        cnt += __popc(m);
    }
    if (lane == 0) g_cnt[b][c] = cnt;
}

// ---------------------------------------------------------------------------
// Kernel 3: clustered flash attention over gathered members.
// Block = (k, c, b). 256 threads as 16x16:
//   S tile:  rows ty*4+a (a<4), cols tx+16*m (m<4)
//   O tile:  rows ty*4+a,       cols {4*tx+q, 64+4*tx+q} (q<4)
// ---------------------------------------------------------------------------
extern __shared__ float sm_[];

__global__ __launch_bounds__(256, 1)
void attn_kernel(const float* __restrict__ query,
                 const float* __restrict__ value,
                 float* __restrict__ out) {
    float* Qs = sm_;                       // BM * SKQ
    float* Ks = Qs + BM * SKQ;             // BN * SKQ
    float* Vs = Ks + BN * SKQ;             // BN * SKQ
    float* Ss = Vs + BN * SKQ;             // BM * SSS
    int*   idx_s = (int*)(Ss + BM * SSS);  // L_

    const int k = blockIdx.x;
    const int c = blockIdx.y;
    const int b = blockIdx.z;
    const int tid = threadIdx.x;
    const int ty = tid >> 4;
    const int tx = tid & 15;

    const int nc = g_cnt[b][c];
    if (nc == 0) return;

    for (int t = tid; t < nc; t += 256) idx_s[t] = g_idx[b][c][t];
    __syncthreads();

    const float scale = 0.08838834764831845f;   // 1/sqrt(128)

    for (int i0 = 0; i0 < nc; i0 += BM) {
        const int ni = min(BM, nc - i0);

        // ---- load Q tile (gathered rows, pre-scaled), zero-pad extra rows
        for (int t = tid; t < BM * 32; t += 256) {    // float4 units
            int r = t >> 5, d4 = (t & 31) << 2;
            float4 v;
            if (r < ni) {
                const float* src = query +
                    ((((size_t)b * L_ + idx_s[i0 + r]) * V_ + k) * D_ + d4);
                v = *(const float4*)src;
                v.x *= scale; v.y *= scale; v.z *= scale; v.w *= scale;
            } else {
                v = make_float4(0.f, 0.f, 0.f, 0.f);
            }
            *(float4*)&Qs[r * SKQ + d4] = v;
        }

        float O[4][8];
        float mrow[4], lrow[4];
#pragma unroll
        for (int a = 0; a < 4; a++) {
            mrow[a] = -1e30f; lrow[a] = 0.f;
#pragma unroll
            for (int x = 0; x < 8; x++) O[a][x] = 0.f;
        }

        for (int j0 = 0; j0 < nc; j0 += BN) {
            const int nj = min(BN, nc - j0);
            __syncthreads();   // Qs ready / previous consumers of Ks,Vs,Ss done

            // ---- load K (sumK rows) and V tiles, zero-pad
            for (int t = tid; t < BN * 32; t += 256) {
                int r = t >> 5, d4 = (t & 31) << 2;
                float4 kv, vv;
                if (r < nj) {
                    int j = idx_s[j0 + r];
                    kv = *(const float4*)(g_sumK + ((size_t)b * L_ + j) * D_ + d4);
                    vv = *(const float4*)(value +
                         ((((size_t)b * L_ + j) * V_ + k) * D_ + d4));
                } else {
                    kv = make_float4(0.f, 0.f, 0.f, 0.f);
                    vv = kv;
                }
                *(float4*)&Ks[r * SKQ + d4] = kv;
                *(float4*)&Vs[r * SKQ + d4] = vv;
            }
            __syncthreads();

            // ---- S = Q * K^T  (per-thread 4x4)
            float acc[4][4];
#pragma unroll
            for (int a = 0; a < 4; a++)
#pragma unroll
                for (int m = 0; m < 4; m++) acc[a][m] = 0.f;

#pragma unroll 2
            for (int d = 0; d < D_; d += 4) {
                float4 qa[4], kb[4];
#pragma unroll
                for (int a = 0; a < 4; a++)
                    qa[a] = *(const float4*)&Qs[(ty * 4 + a) * SKQ + d];
#pragma unroll
                for (int m = 0; m < 4; m++)
                    kb[m] = *(const float4*)&Ks[(tx + 16 * m) * SKQ + d];
#pragma unroll
                for (int a = 0; a < 4; a++)
#pragma unroll
                    for (int m = 0; m < 4; m++) {
                        acc[a][m] += qa[a].x * kb[m].x;
                        acc[a][m] += qa[a].y * kb[m].y;
                        acc[a][m] += qa[a].z * kb[m].z;
                        acc[a][m] += qa[a].w * kb[m].w;
                    }
            }

            // ---- online softmax update (rows shared by 16-lane tx-groups)
#pragma unroll
            for (int a = 0; a < 4; a++) {
                float s[4];
                float mx = -1e30f;
#pragma unroll
                for (int m = 0; m < 4; m++) {
                    int col = tx + 16 * m;
                    s[m] = (col < nj) ? acc[a][m] : -1e30f;
                    mx = fmaxf(mx, s[m]);
                }
                mx = fmaxf(mx, __shfl_xor_sync(0xffffffffu, mx, 1));
                mx = fmaxf(mx, __shfl_xor_sync(0xffffffffu, mx, 2));
                mx = fmaxf(mx, __shfl_xor_sync(0xffffffffu, mx, 4));
                mx = fmaxf(mx, __shfl_xor_sync(0xffffffffu, mx, 8));

                float mnew = fmaxf(mrow[a], mx);
                float f = __expf(mrow[a] - mnew);
                float ps = 0.f;
#pragma unroll
                for (int m = 0; m < 4; m++) {
                    float p = __expf(s[m] - mnew);
                    ps += p;
                    Ss[(ty * 4 + a) * SSS + tx + 16 * m] = p;
                }
                ps += __shfl_xor_sync(0xffffffffu, ps, 1);
                ps += __shfl_xor_sync(0xffffffffu, ps, 2);
                ps += __shfl_xor_sync(0xffffffffu, ps, 4);
                ps += __shfl_xor_sync(0xffffffffu, ps, 8);

                lrow[a] = lrow[a] * f + ps;
                mrow[a] = mnew;
#pragma unroll
                for (int x = 0; x < 8; x++) O[a][x] *= f;
            }
            __syncthreads();   // Ss complete before consumption

            // ---- O += P * V  (padded cols have p == 0)
#pragma unroll 4
            for (int j = 0; j < BN; j++) {
                float pv[4];
#pragma unroll
                for (int a = 0; a < 4; a++) pv[a] = Ss[(ty * 4 + a) * SSS + j];
                float4 v0 = *(const float4*)&Vs[j * SKQ + 4 * tx];
                float4 v1 = *(const float4*)&Vs[j * SKQ + 64 + 4 * tx];
#pragma unroll
                for (int a = 0; a < 4; a++) {
                    O[a][0] += pv[a] * v0.x;
                    O[a][1] += pv[a] * v0.y;
                    O[a][2] += pv[a] * v0.z;
                    O[a][3] += pv[a] * v0.w;
                    O[a][4] += pv[a] * v1.x;
                    O[a][5] += pv[a] * v1.y;
                    O[a][6] += pv[a] * v1.z;
                    O[a][7] += pv[a] * v1.w;
                }
            }
        }

        // ---- epilogue: normalize and scatter rows back
#pragma unroll
        for (int a = 0; a < 4; a++) {
            int r = ty * 4 + a;
            if (r < ni) {
                int i = idx_s[i0 + r];
                float inv = 1.f / lrow[a];
                float* dst = out + (((size_t)b * L_ + i) * V_ + k) * D_;
                float4 o0 = make_float4(O[a][0] * inv, O[a][1] * inv,
                                        O[a][2] * inv, O[a][3] * inv);
                float4 o1 = make_float4(O[a][4] * inv, O[a][5] * inv,
                                        O[a][6] * inv, O[a][7] * inv);
                *(float4*)(dst + 4 * tx) = o0;
                *(float4*)(dst + 64 + 4 * tx) = o1;
            }
        }
        __syncthreads();   // all reads of idx_s/Ss done before next i-tile reload
    }
}

static const int SMEM_BYTES =
    (BM * SKQ + 2 * BN * SKQ + BM * SSS) * (int)sizeof(float) + L_ * (int)sizeof(int);

extern "C" void kernel_launch(void* const* d_in, const int* in_sizes, int n_in,
                              void* d_out, int out_size) {
    (void)in_sizes; (void)n_in; (void)out_size;
    const float* query = (const float*)d_in[0];
    const float* key   = (const float*)d_in[1];
    const float* value = (const float*)d_in[2];
    const int*   label = (const int*)d_in[3];
    float* out = (float*)d_out;

    sumk_kernel<<<B_ * L_, 128>>>(key);
    build_idx_kernel<<<dim3(NC_, B_), 32>>>(label);
    cudaFuncSetAttribute(attn_kernel,
                         cudaFuncAttributeMaxDynamicSharedMemorySize, SMEM_BYTES);
    attn_kernel<<<dim3(V_, NC_, B_), 256, SMEM_BYTES>>>(query, value, out);
}

// round 2
// speedup vs baseline: 1.3583x; 1.3583x over previous
#include <cuda_runtime.h>
#include <cuda_bf16.h>

#define B_ 2
#define L_ 512
#define V_ 64
#define D_ 128
#define NC_ 8
#define BM 64
#define BN 64

// ---- static device scratch (no allocations allowed) ----
__device__ float g_sumK[B_ * L_ * D_];
__device__ int   g_idx[B_][NC_][L_];
__device__ int   g_cnt[B_][NC_];

// ---------------------------------------------------------------------------
// Kernel 1: sumK[b,l,d] = sum_v key[b,l,v,d]   (float4, DRAM-bound)
// ---------------------------------------------------------------------------
__global__ void sumk_kernel(const float4* __restrict__ key4) {
    int t  = blockIdx.x * blockDim.x + threadIdx.x;  // 0 .. B_*L_*32-1
    int bl = t >> 5, g = t & 31;
    const float4* p = key4 + (size_t)bl * (V_ * D_ / 4) + g;
    float sx = 0.f, sy = 0.f, sz = 0.f, sw = 0.f;
#pragma unroll 8
    for (int v = 0; v < V_; v++) {
        float4 q = p[(size_t)v * (D_ / 4)];
        sx += q.x; sy += q.y; sz += q.z; sw += q.w;
    }
    ((float4*)g_sumK)[t] = make_float4(sx, sy, sz, sw);
}

// ---------------------------------------------------------------------------
// Kernel 2: deterministic per-(b,c) index lists via ballot compaction
// ---------------------------------------------------------------------------
__global__ void build_idx_kernel(const int* __restrict__ label) {
    int c = blockIdx.x, b = blockIdx.y;
    int lane = threadIdx.x;
    int cnt = 0;
    for (int l0 = 0; l0 < L_; l0 += 32) {
        int l = l0 + lane;
        int lbl = label[b * L_ + l];
        unsigned m = __ballot_sync(0xffffffffu, lbl == c);
        if (lbl == c) {
            int pos = cnt + __popc(m & ((1u << lane) - 1u));
            g_idx[b][c][pos] = l;
        }
        cnt += __popc(m);
    }
    if (lane == 0) g_cnt[b][c] = cnt;
}

// ---------------------------------------------------------------------------
// Kernel 3: clustered flash attention, 128 threads, 2 CTAs/SM.
//   thread grid: ty = tid>>3 (0..15), tx = tid&7 (0..7)
//   S tile:  rows ty*4+a (a<4), cols tx+8m (m<8)   -> acc[4][8]
//   O tile:  rows ty*4+a,       d-cols 4*tx+32*q+e -> O[4][16]
//   Tiles Q/K/V: 64 rows x 32 float4, XOR-swizzled (g ^= r&7). No score smem:
//   P lives in acc[][] and reaches PV through warp shuffles.
// ---------------------------------------------------------------------------
extern __shared__ float sm_[];

__global__ __launch_bounds__(128, 2)
void attn_kernel(const float* __restrict__ query,
                 const float* __restrict__ value,
                 float* __restrict__ out) {
    float4* Qs = (float4*)sm_;        // BM*32
    float4* Ks = Qs + BM * 32;        // BN*32
    float4* Vs = Ks + BN * 32;        // BN*32

    const int k = blockIdx.x, c = blockIdx.y, b = blockIdx.z;
    const int tid  = threadIdx.x;
    const int tx   = tid & 7;
    const int ty   = tid >> 3;
    const int lane = tid & 31;
    const int w    = tid >> 5;

    const int nc = g_cnt[b][c];
    if (nc == 0) return;
    const int* __restrict__ idx = g_idx[b][c];
    const float scale = 0.08838834764831845f;   // 1/sqrt(128)

    const int r0 = ty * 4;            // first of this thread's 4 rows
    const int rx = r0 & 7;            // swizzle phase helpers (rows r0..r0+3)

    for (int i0 = 0; i0 < nc; i0 += BM) {
        const int ni = min(BM, nc - i0);
        const bool active = (w * 16) < ni;     // warp-level row skip

        __syncthreads();   // prior readers of Qs done
        // ---- load Q tile (gathered, pre-scaled), zero-pad rows >= ni
        for (int t = tid; t < BM * 32; t += 128) {
            int r = t >> 5, g = t & 31;
            float4 v = make_float4(0.f, 0.f, 0.f, 0.f);
            if (r < ni) {
                v = ((const float4*)query)[
                        (((size_t)b * L_ + idx[i0 + r]) * V_ + k) * 32 + g];
                v.x *= scale; v.y *= scale; v.z *= scale; v.w *= scale;
            }
            Qs[r * 32 + (g ^ (r & 7))] = v;
        }

        float O[4][16];
        float mrow[4], lrow[4];
#pragma unroll
        for (int a = 0; a < 4; a++) {
            mrow[a] = -1e30f; lrow[a] = 0.f;
#pragma unroll
            for (int x = 0; x < 16; x++) O[a][x] = 0.f;
        }

        for (int j0 = 0; j0 < nc; j0 += BN) {
            const int nj = min(BN, nc - j0);
            const int M8 = (nj + 7) >> 3;
            __syncthreads();   // Qs ready / prior readers of Ks,Vs done

            // ---- load K (sumK) + V tiles, zero-pad rows >= nj
            for (int t = tid; t < BN * 32; t += 128) {
                int r = t >> 5, g = t & 31;
                float4 kv = make_float4(0.f, 0.f, 0.f, 0.f), vv = kv;
                if (r < nj) {
                    int j = idx[j0 + r];
                    kv = ((const float4*)g_sumK)[((size_t)b * L_ + j) * 32 + g];
                    vv = ((const float4*)value)[
                            (((size_t)b * L_ + j) * V_ + k) * 32 + g];
                }
                int gs = g ^ (r & 7);
                Ks[r * 32 + gs] = kv;
                Vs[r * 32 + gs] = vv;
            }
            __syncthreads();

            if (active) {
                // ---- S = Q * K^T
                float acc[4][8];
#pragma unroll
                for (int a = 0; a < 4; a++)
#pragma unroll
                    for (int m = 0; m < 8; m++) acc[a][m] = 0.f;

                if (M8 == 8) {
                    // full tile: 12 broadcast-free LDS.128 per d-step, 128 FFMA
#pragma unroll 2
                    for (int ds = 0; ds < 32; ds++) {
                        float4 qa[4], kb[8];
#pragma unroll
                        for (int a = 0; a < 4; a++)
                            qa[a] = Qs[(r0 + a) * 32 + (ds ^ ((rx + a) & 7))];
#pragma unroll
                        for (int m = 0; m < 8; m++)
                            kb[m] = Ks[(tx + 8 * m) * 32 + (ds ^ tx)];
#pragma unroll
                        for (int a = 0; a < 4; a++)
#pragma unroll
                            for (int m = 0; m < 8; m++) {
                                acc[a][m] += qa[a].x * kb[m].x;
                                acc[a][m] += qa[a].y * kb[m].y;
                                acc[a][m] += qa[a].z * kb[m].z;
                                acc[a][m] += qa[a].w * kb[m].w;
                            }
                    }
                } else {
                    // partial tile: only active column groups
#pragma unroll
                    for (int m = 0; m < 8; m++) {
                        if (m >= M8) break;
                        const int row = tx + 8 * m;
#pragma unroll 4
                        for (int ds = 0; ds < 32; ds++) {
                            float4 kb = Ks[row * 32 + (ds ^ tx)];
#pragma unroll
                            for (int a = 0; a < 4; a++) {
                                float4 qa = Qs[(r0 + a) * 32 + (ds ^ ((rx + a) & 7))];
                                acc[a][m] += qa.x * kb.x + qa.y * kb.y +
                                             qa.z * kb.z + qa.w * kb.w;
                            }
                        }
                    }
                }

                // ---- online softmax (row groups = 8 tx lanes)
#pragma unroll
                for (int a = 0; a < 4; a++) {
                    float mx = -1e30f;
#pragma unroll
                    for (int m = 0; m < 8; m++) {
                        if (tx + 8 * m >= nj) acc[a][m] = -1e30f;
                        mx = fmaxf(mx, acc[a][m]);
                    }
                    mx = fmaxf(mx, __shfl_xor_sync(0xffffffffu, mx, 1));
                    mx = fmaxf(mx, __shfl_xor_sync(0xffffffffu, mx, 2));
                    mx = fmaxf(mx, __shfl_xor_sync(0xffffffffu, mx, 4));

                    float mnew = fmaxf(mrow[a], mx);
                    float f = __expf(mrow[a] - mnew);
                    float ps = 0.f;
#pragma unroll
                    for (int m = 0; m < 8; m++) {
                        float p = __expf(acc[a][m] - mnew);
                        acc[a][m] = p;      // P kept in registers
                        ps += p;
                    }
                    ps += __shfl_xor_sync(0xffffffffu, ps, 1);
                    ps += __shfl_xor_sync(0xffffffffu, ps, 2);
                    ps += __shfl_xor_sync(0xffffffffu, ps, 4);

                    lrow[a] = lrow[a] * f + ps;
                    mrow[a] = mnew;
#pragma unroll
                    for (int x = 0; x < 16; x++) O[a][x] *= f;
                }

                // ---- O += P * V  (P via shuffle; dynamic j trip)
#pragma unroll
                for (int m = 0; m < 8; m++) {
                    int rem = nj - 8 * m;
                    if (rem <= 0) break;
                    int jmax = rem < 8 ? rem : 8;
#pragma unroll 4
                    for (int jj = 0; jj < jmax; jj++) {
                        int src = (lane & 24) | jj;
                        float p0 = __shfl_sync(0xffffffffu, acc[0][m], src);
                        float p1 = __shfl_sync(0xffffffffu, acc[1][m], src);
                        float p2 = __shfl_sync(0xffffffffu, acc[2][m], src);
                        float p3 = __shfl_sync(0xffffffffu, acc[3][m], src);
                        int j = 8 * m + jj;
#pragma unroll
                        for (int q = 0; q < 4; q++) {
                            float4 v = Vs[j * 32 + ((tx + 8 * q) ^ jj)];
                            O[0][q*4+0] += p0 * v.x; O[0][q*4+1] += p0 * v.y;
                            O[0][q*4+2] += p0 * v.z; O[0][q*4+3] += p0 * v.w;
                            O[1][q*4+0] += p1 * v.x; O[1][q*4+1] += p1 * v.y;
                            O[1][q*4+2] += p1 * v.z; O[1][q*4+3] += p1 * v.w;
                            O[2][q*4+0] += p2 * v.x; O[2][q*4+1] += p2 * v.y;
                            O[2][q*4+2] += p2 * v.z; O[2][q*4+3] += p2 * v.w;
                            O[3][q*4+0] += p3 * v.x; O[3][q*4+1] += p3 * v.y;
                            O[3][q*4+2] += p3 * v.z; O[3][q*4+3] += p3 * v.w;
                        }
                    }
                }
            }
        }

        // ---- epilogue: normalize, scatter rows (d-cols 4*tx + 32*q)
        if (active) {
#pragma unroll
            for (int a = 0; a < 4; a++) {
                int r = r0 + a;
                if (r < ni) {
                    int i = idx[i0 + r];
                    float inv = 1.f / lrow[a];
                    float* dst = out + (((size_t)b * L_ + i) * V_ + k) * D_;
#pragma unroll
                    for (int q = 0; q < 4; q++) {
                        float4 o = make_float4(O[a][q*4+0] * inv, O[a][q*4+1] * inv,
                                               O[a][q*4+2] * inv, O[a][q*4+3] * inv);
                        *(float4*)(dst + 4 * tx + 32 * q) = o;
                    }
                }
            }
        }
    }
}

static const int SMEM_BYTES = 3 * BM * 32 * (int)sizeof(float4);   // 96 KB

extern "C" void kernel_launch(void* const* d_in, const int* in_sizes, int n_in,
                              void* d_out, int out_size) {
    (void)in_sizes; (void)n_in; (void)out_size;
    const float* query = (const float*)d_in[0];
    const float* key   = (const float*)d_in[1];
    const float* value = (const float*)d_in[2];
    const int*   label = (const int*)d_in[3];
    float* out = (float*)d_out;

    sumk_kernel<<<(B_ * L_ * 32) / 256, 256>>>((const float4*)key);
    build_idx_kernel<<<dim3(NC_, B_), 32>>>(label);
    cudaFuncSetAttribute(attn_kernel,
                         cudaFuncAttributeMaxDynamicSharedMemorySize, SMEM_BYTES);
    attn_kernel<<<dim3(V_, NC_, B_), 128, SMEM_BYTES>>>(query, value, out);
}